// round 4
// baseline (speedup 1.0000x reference)
#include <cuda_runtime.h>
#include <mma.h>

using namespace nvcuda;

constexpr int Bb = 8;
constexpr int Nn = 1024;
constexpr int Cc = 768;
constexpr int Hh = 12;
constexpr int HD = 64;
constexpr int Mm = Bb * Nn;   // 8192

// Scratch (allowed: __device__ globals, no allocation)
__device__ __align__(16) float g_q[(size_t)Bb * Hh * Nn * HD];
__device__ __align__(16) float g_k[(size_t)Bb * Hh * Nn * HD];
__device__ __align__(16) float g_v[(size_t)Bb * Hh * Nn * HD];
__device__ __align__(16) float g_ao[(size_t)Mm * Cc];

using FragA  = wmma::fragment<wmma::matrix_a, 16, 16, 8, wmma::precision::tf32, wmma::row_major>;
using FragBr = wmma::fragment<wmma::matrix_b, 16, 16, 8, wmma::precision::tf32, wmma::row_major>;
using FragBc = wmma::fragment<wmma::matrix_b, 16, 16, 8, wmma::precision::tf32, wmma::col_major>;
using FragC  = wmma::fragment<wmma::accumulator, 16, 16, 8, float>;

template <class F>
__device__ __forceinline__ void to_tf32(F& f) {
#pragma unroll
    for (int i = 0; i < f.num_elements; i++) f.x[i] = wmma::__float_to_tf32(f.x[i]);
}

// ---------------------------------------------------------------------------
// GEMM: C[M,Ncols] = A[M,768] @ Bm[768,Ncols] + bias   (tf32 wmma, 128x128 tile)
// MODE 0: QKV — scatter into g_q/g_k/g_v laid out [B,H,N,64]
// MODE 1: proj — A is g_ao, plain row-major store to out
// Bias folded in as a rank-1 pre-step (A column of ones x bias row).
// ---------------------------------------------------------------------------
template <int MODE>
__global__ void __launch_bounds__(256) gemm_kernel(const float* __restrict__ Ain,
                                                   const float* __restrict__ Bm,
                                                   const float* __restrict__ bias,
                                                   float* __restrict__ out, int Ncols) {
    __shared__ float As[128][36];
    __shared__ float Bs[32][132];

    const float* A = (MODE == 1) ? (const float*)g_ao : Ain;
    const int m0 = blockIdx.y * 128;
    const int n0 = blockIdx.x * 128;
    const int tid = threadIdx.x;
    const int warp = tid >> 5;
    const int wm = warp >> 2;   // 0..1 -> 64 rows
    const int wn = warp & 3;    // 0..3 -> 32 cols

    FragC acc[4][2];
#pragma unroll
    for (int i = 0; i < 4; i++)
#pragma unroll
        for (int j = 0; j < 2; j++) wmma::fill_fragment(acc[i][j], 0.0f);

    // ---- bias as rank-1 update: one k=8 step with A=[1,0..0], B rows=[bias;0..] ----
#pragma unroll
    for (int t = 0; t < 4; t++) {
        int idx = tid + t * 256;
        int r = idx >> 3, c = idx & 7;
        As[r][c] = (c == 0) ? 1.0f : 0.0f;
    }
#pragma unroll
    for (int t = 0; t < 4; t++) {
        int idx = tid + t * 256;
        int r = idx >> 7, c = idx & 127;
        Bs[r][c] = (r == 0) ? bias[n0 + c] : 0.0f;
    }
    __syncthreads();
    {
        FragA af[4];
        FragBr bf[2];
#pragma unroll
        for (int i = 0; i < 4; i++) {
            wmma::load_matrix_sync(af[i], &As[wm * 64 + i * 16][0], 36);
            to_tf32(af[i]);
        }
#pragma unroll
        for (int j = 0; j < 2; j++) {
            wmma::load_matrix_sync(bf[j], &Bs[0][wn * 32 + j * 16], 132);
            to_tf32(bf[j]);
        }
#pragma unroll
        for (int i = 0; i < 4; i++)
#pragma unroll
            for (int j = 0; j < 2; j++) wmma::mma_sync(acc[i][j], af[i], bf[j], acc[i][j]);
    }
    __syncthreads();

    // ---- main K loop ----
    for (int kt = 0; kt < Cc / 32; kt++) {
        const int k0 = kt * 32;
#pragma unroll
        for (int t = 0; t < 4; t++) {
            int idx = tid + t * 256;
            int r = idx >> 3, c4 = idx & 7;
            float4 v = *(const float4*)(A + (size_t)(m0 + r) * Cc + k0 + c4 * 4);
            *(float4*)&As[r][c4 * 4] = v;
        }
#pragma unroll
        for (int t = 0; t < 4; t++) {
            int idx = tid + t * 256;
            int r = idx >> 5, c4 = idx & 31;
            float4 v = *(const float4*)(Bm + (size_t)(k0 + r) * Ncols + n0 + c4 * 4);
            *(float4*)&Bs[r][c4 * 4] = v;
        }
        __syncthreads();
#pragma unroll
        for (int kk = 0; kk < 32; kk += 8) {
            FragA af[4];
            FragBr bf[2];
#pragma unroll
            for (int i = 0; i < 4; i++) {
                wmma::load_matrix_sync(af[i], &As[wm * 64 + i * 16][kk], 36);
                to_tf32(af[i]);
            }
#pragma unroll
            for (int j = 0; j < 2; j++) {
                wmma::load_matrix_sync(bf[j], &Bs[kk][wn * 32 + j * 16], 132);
                to_tf32(bf[j]);
            }
#pragma unroll
            for (int i = 0; i < 4; i++)
#pragma unroll
                for (int j = 0; j < 2; j++) wmma::mma_sync(acc[i][j], af[i], bf[j], acc[i][j]);
        }
        __syncthreads();
    }

    // ---- store ----
#pragma unroll
    for (int i = 0; i < 4; i++) {
#pragma unroll
        for (int j = 0; j < 2; j++) {
            const int m = m0 + wm * 64 + i * 16;
            const int cg = n0 + wn * 32 + j * 16;
            if (MODE == 1) {
                wmma::store_matrix_sync(out + (size_t)m * Ncols + cg, acc[i][j], Ncols,
                                        wmma::mem_row_major);
            } else {
                // cg in [0,2304): which = q/k/v, then head h and dim d (16-col frag
                // never crosses a 64-chunk boundary since cg % 16 == 0)
                const int which = cg / Cc;
                const int c = cg % Cc;
                const int h = c >> 6, d = c & 63;
                float* arr = (which == 0) ? g_q : (which == 1) ? g_k : g_v;
                const int b = m >> 10, n = m & 1023;
                wmma::store_matrix_sync(arr + (size_t)((b * Hh + h) * Nn + n) * HD + d,
                                        acc[i][j], HD, wmma::mem_row_major);
            }
        }
    }
}

// ---------------------------------------------------------------------------
// Flash attention: one CTA per (bh, 128-query tile). Online softmax in smem.
// S = (Q*scale) K^T via wmma; P,V -> O accumulation via wmma with O in smem.
// ---------------------------------------------------------------------------
constexpr int ATTN_SMEM = (3 * 128 * 68 + 128 * 132 + 3 * 128) * 4;  // 173568 B

__global__ void __launch_bounds__(256) attn_kernel() {
    extern __shared__ float sm[];
    float* Qs   = sm;                // [128][68]
    float* KVs  = Qs + 128 * 68;     // [128][68]  (K tile, then reused for V)
    float* Os   = KVs + 128 * 68;    // [128][68]
    float* Ss   = Os + 128 * 68;     // [128][132]
    float* m_s  = Ss + 128 * 132;    // [128]
    float* l_s  = m_s + 128;         // [128]
    float* al_s = l_s + 128;         // [128]

    const int tid = threadIdx.x;
    const int warp = tid >> 5;
    const int n0 = blockIdx.x * 128;  // query tile
    const int bh = blockIdx.y;        // 0..95
    const float* Qg = g_q + (size_t)bh * Nn * HD;
    const float* Kg = g_k + (size_t)bh * Nn * HD;
    const float* Vg = g_v + (size_t)bh * Nn * HD;

    // load Q tile pre-scaled by 1/sqrt(64) = 0.125 (exact power of two)
#pragma unroll
    for (int t = 0; t < 8; t++) {
        int idx = tid + t * 256;
        int r = idx >> 4, c4 = idx & 15;
        float4 v = *(const float4*)(Qg + (size_t)(n0 + r) * HD + c4 * 4);
        v.x *= 0.125f; v.y *= 0.125f; v.z *= 0.125f; v.w *= 0.125f;
        *(float4*)&Qs[r * 68 + c4 * 4] = v;
    }
#pragma unroll
    for (int t = 0; t < 8; t++) {
        int idx = tid + t * 256;
        int r = idx >> 4, c4 = idx & 15;
        *(float4*)&Os[r * 68 + c4 * 4] = make_float4(0.f, 0.f, 0.f, 0.f);
    }
    if (tid < 128) {
        m_s[tid] = -1e30f;
        l_s[tid] = 0.0f;
    }
    __syncthreads();

    for (int kt = 0; kt < Nn / 128; kt++) {
        // ---- load K tile ----
#pragma unroll
        for (int t = 0; t < 8; t++) {
            int idx = tid + t * 256;
            int r = idx >> 4, c4 = idx & 15;
            *(float4*)&KVs[r * 68 + c4 * 4] =
                *(const float4*)(Kg + (size_t)(kt * 128 + r) * HD + c4 * 4);
        }
        __syncthreads();

        // ---- S = Q K^T (128x128) ----
        {
            const int wm = warp >> 2, wn = warp & 3;  // warp tile 64x32
            FragC accS[4][2];
#pragma unroll
            for (int i = 0; i < 4; i++)
#pragma unroll
                for (int j = 0; j < 2; j++) wmma::fill_fragment(accS[i][j], 0.0f);
#pragma unroll
            for (int kk = 0; kk < HD; kk += 8) {
                FragA af[4];
                FragBc bf[2];
#pragma unroll
                for (int i = 0; i < 4; i++) {
                    wmma::load_matrix_sync(af[i], &Qs[(wm * 64 + i * 16) * 68 + kk], 68);
                    to_tf32(af[i]);
                }
#pragma unroll
                for (int j = 0; j < 2; j++) {
                    // K tile is [n][k] row-major == B (k x n) col-major, ldm 68
                    wmma::load_matrix_sync(bf[j], &KVs[(wn * 32 + j * 16) * 68 + kk], 68);
                    to_tf32(bf[j]);
                }
#pragma unroll
                for (int i = 0; i < 4; i++)
#pragma unroll
                    for (int j = 0; j < 2; j++)
                        wmma::mma_sync(accS[i][j], af[i], bf[j], accS[i][j]);
            }
#pragma unroll
            for (int i = 0; i < 4; i++)
#pragma unroll
                for (int j = 0; j < 2; j++)
                    wmma::store_matrix_sync(&Ss[(wm * 64 + i * 16) * 132 + wn * 32 + j * 16],
                                            accS[i][j], 132, wmma::mem_row_major);
        }
        __syncthreads();

        // ---- online softmax (2 threads per row, 64 cols each) ----
        {
            const int r = tid >> 1;
            float* row = Ss + r * 132 + (tid & 1) * 64;
            const float mo = m_s[r];
            float mx = -1e30f;
#pragma unroll 8
            for (int c = 0; c < 64; c++) mx = fmaxf(mx, row[c]);
            mx = fmaxf(mx, __shfl_xor_sync(0xffffffffu, mx, 1));
            const float mn = fmaxf(mo, mx);
            float ssum = 0.0f;
#pragma unroll 8
            for (int c = 0; c < 64; c++) {
                float p = __expf(row[c] - mn);
                row[c] = p;
                ssum += p;
            }
            ssum += __shfl_xor_sync(0xffffffffu, ssum, 1);
            if ((tid & 1) == 0) {
                const float a = __expf(mo - mn);
                al_s[r] = a;
                m_s[r] = mn;
                l_s[r] = l_s[r] * a + ssum;
            }
        }
        __syncthreads();

        // ---- load V tile (reuse K buffer) + rescale O by alpha ----
#pragma unroll
        for (int t = 0; t < 8; t++) {
            int idx = tid + t * 256;
            int r = idx >> 4, c4 = idx & 15;
            *(float4*)&KVs[r * 68 + c4 * 4] =
                *(const float4*)(Vg + (size_t)(kt * 128 + r) * HD + c4 * 4);
        }
#pragma unroll
        for (int t = 0; t < 32; t++) {
            int idx = tid + t * 256;
            int r = idx >> 6, c = idx & 63;
            Os[r * 68 + c] *= al_s[r];
        }
        __syncthreads();

        // ---- O += P V (128x64) ----
        {
            const int wm = warp >> 1, wn = warp & 1;  // warp tile 32x32
            FragC accO[2][2];
#pragma unroll
            for (int i = 0; i < 2; i++)
#pragma unroll
                for (int j = 0; j < 2; j++)
                    wmma::load_matrix_sync(accO[i][j],
                                           &Os[(wm * 32 + i * 16) * 68 + wn * 32 + j * 16], 68,
                                           wmma::mem_row_major);
#pragma unroll
            for (int kk = 0; kk < 128; kk += 8) {
                FragA af[2];
                FragBr bf[2];
#pragma unroll
                for (int i = 0; i < 2; i++) {
                    wmma::load_matrix_sync(af[i], &Ss[(wm * 32 + i * 16) * 132 + kk], 132);
                    to_tf32(af[i]);
                }
#pragma unroll
                for (int j = 0; j < 2; j++) {
                    wmma::load_matrix_sync(bf[j], &KVs[kk * 68 + wn * 32 + j * 16], 68);
                    to_tf32(bf[j]);
                }
#pragma unroll
                for (int i = 0; i < 2; i++)
#pragma unroll
                    for (int j = 0; j < 2; j++)
                        wmma::mma_sync(accO[i][j], af[i], bf[j], accO[i][j]);
            }
#pragma unroll
            for (int i = 0; i < 2; i++)
#pragma unroll
                for (int j = 0; j < 2; j++)
                    wmma::store_matrix_sync(&Os[(wm * 32 + i * 16) * 68 + wn * 32 + j * 16],
                                            accO[i][j], 68, wmma::mem_row_major);
        }
        __syncthreads();
    }

    // ---- epilogue: normalize and write to [B, N, C] with C-index h*64+d ----
    const int b = bh / Hh, h = bh % Hh;
#pragma unroll
    for (int t = 0; t < 32; t++) {
        int idx = tid + t * 256;
        int r = idx >> 6, c = idx & 63;
        g_ao[(size_t)(b * Nn + n0 + r) * Cc + h * HD + c] = Os[r * 68 + c] * (1.0f / l_s[r]);
    }
}

// ---------------------------------------------------------------------------
extern "C" void kernel_launch(void* const* d_in, const int* in_sizes, int n_in,
                              void* d_out, int out_size) {
    const float* x      = (const float*)d_in[0];
    const float* w_qkv  = (const float*)d_in[1];
    const float* b_qkv  = (const float*)d_in[2];
    const float* w_proj = (const float*)d_in[3];
    const float* b_proj = (const float*)d_in[4];
    float* out = (float*)d_out;

    cudaFuncSetAttribute(attn_kernel, cudaFuncAttributeMaxDynamicSharedMemorySize, ATTN_SMEM);

    dim3 blk(256);
    // 1) QKV GEMM: [8192,768] @ [768,2304] + bias -> scatter to Q/K/V
    gemm_kernel<0><<<dim3((3 * Cc) / 128, Mm / 128), blk>>>(x, w_qkv, b_qkv, nullptr, 3 * Cc);
    // 2) attention per (bh, q-tile)
    attn_kernel<<<dim3(Nn / 128, Bb * Hh), blk, ATTN_SMEM>>>();
    // 3) output projection: [8192,768] @ [768,768] + bias -> d_out
    gemm_kernel<1><<<dim3(Cc / 128, Mm / 128), blk>>>(nullptr, w_proj, b_proj, out, Cc);
}

// round 9
// speedup vs baseline: 2.3414x; 2.3414x over previous
#include <cuda_runtime.h>
#include <cuda_fp16.h>
#include <mma.h>
#include <cstdint>

using namespace nvcuda;

constexpr int Bb = 8;
constexpr int Nn = 1024;
constexpr int Cc = 768;
constexpr int Hh = 12;
constexpr int HD = 64;
constexpr int Mm = Bb * Nn;   // 8192

// Scratch (allowed: __device__ globals, no allocation) — fp16 activations
__device__ __align__(16) __half g_q[(size_t)Bb * Hh * Nn * HD];
__device__ __align__(16) __half g_k[(size_t)Bb * Hh * Nn * HD];
__device__ __align__(16) __half g_v[(size_t)Bb * Hh * Nn * HD];
__device__ __align__(16) __half g_ao[(size_t)Mm * Cc];

using FragA  = wmma::fragment<wmma::matrix_a, 16, 16, 16, __half, wmma::row_major>;
using FragBr = wmma::fragment<wmma::matrix_b, 16, 16, 16, __half, wmma::row_major>;
using FragBc = wmma::fragment<wmma::matrix_b, 16, 16, 16, __half, wmma::col_major>;
using FragC  = wmma::fragment<wmma::accumulator, 16, 16, 16, float>;

// ---------------------------------------------------------------------------
// GEMM: C[M,Ncols] = A[M,768] @ Bm[768,Ncols] + bias   (fp16 wmma, 128x128 tile)
// MODE 0: A = x (fp32), scatter fp16 into g_q/g_k/g_v laid out [B,H,N,64]
// MODE 1: A = g_ao (fp16), fp32 row-major store to out
// Bias folded in as a rank-1 pre-step (A column of ones x bias row).
// ---------------------------------------------------------------------------
template <int MODE>
__global__ void __launch_bounds__(256) gemm_kernel(const float* __restrict__ Ain,
                                                   const float* __restrict__ Bm,
                                                   const float* __restrict__ bias,
                                                   float* __restrict__ out, int Ncols) {
    __shared__ __align__(16) __half As[128][40];   // 32-wide K chunk, pad 8
    __shared__ __align__(16) __half Bs[32][136];   // 128-wide N, pad 8
    __shared__ __align__(16) float stage[8][256];  // per-warp 16x16 fp32 staging (MODE 0)

    const int m0 = blockIdx.y * 128;
    const int n0 = blockIdx.x * 128;
    const int tid = threadIdx.x;
    const int warp = tid >> 5;
    const int lid = tid & 31;
    const int wm = warp >> 2;   // 0..1 -> 64 rows
    const int wn = warp & 3;    // 0..3 -> 32 cols

    FragC acc[4][2];
#pragma unroll
    for (int i = 0; i < 4; i++)
#pragma unroll
        for (int j = 0; j < 2; j++) wmma::fill_fragment(acc[i][j], 0.0f);

    // ---- bias as rank-1 update: one k=16 step with A=[1,0..0], B rows=[bias;0..] ----
#pragma unroll
    for (int t = 0; t < 8; t++) {
        int idx = tid + t * 256;
        int r = idx >> 4, c = idx & 15;
        As[r][c] = __float2half((c == 0) ? 1.0f : 0.0f);
    }
#pragma unroll
    for (int t = 0; t < 8; t++) {
        int idx = tid + t * 256;
        int r = idx >> 7, c = idx & 127;
        Bs[r][c] = __float2half((r == 0) ? bias[n0 + c] : 0.0f);
    }
    __syncthreads();
    {
        FragA af[4];
        FragBr bf[2];
#pragma unroll
        for (int i = 0; i < 4; i++) wmma::load_matrix_sync(af[i], &As[wm * 64 + i * 16][0], 40);
#pragma unroll
        for (int j = 0; j < 2; j++) wmma::load_matrix_sync(bf[j], &Bs[0][wn * 32 + j * 16], 136);
#pragma unroll
        for (int i = 0; i < 4; i++)
#pragma unroll
            for (int j = 0; j < 2; j++) wmma::mma_sync(acc[i][j], af[i], bf[j], acc[i][j]);
    }
    __syncthreads();

    // ---- main K loop: 24 chunks of 32 ----
    for (int kt = 0; kt < Cc / 32; kt++) {
        const int k0 = kt * 32;
        if (MODE == 0) {
            // A fp32 -> fp16
#pragma unroll
            for (int t = 0; t < 4; t++) {
                int idx = tid + t * 256;
                int r = idx >> 3, c4 = idx & 7;
                float4 v = *(const float4*)(Ain + (size_t)(m0 + r) * Cc + k0 + c4 * 4);
                *(__half2*)&As[r][c4 * 4]     = __floats2half2_rn(v.x, v.y);
                *(__half2*)&As[r][c4 * 4 + 2] = __floats2half2_rn(v.z, v.w);
            }
        } else {
            // A already fp16 (g_ao)
#pragma unroll
            for (int t = 0; t < 2; t++) {
                int idx = tid + t * 256;
                int r = idx >> 2, g = idx & 3;
                *(uint4*)&As[r][g * 8] =
                    *(const uint4*)(g_ao + (size_t)(m0 + r) * Cc + k0 + g * 8);
            }
        }
        // B fp32 -> fp16
#pragma unroll
        for (int t = 0; t < 4; t++) {
            int idx = tid + t * 256;
            int r = idx >> 5, c4 = idx & 31;
            float4 v = *(const float4*)(Bm + (size_t)(k0 + r) * Ncols + n0 + c4 * 4);
            *(__half2*)&Bs[r][c4 * 4]     = __floats2half2_rn(v.x, v.y);
            *(__half2*)&Bs[r][c4 * 4 + 2] = __floats2half2_rn(v.z, v.w);
        }
        __syncthreads();
#pragma unroll
        for (int kk = 0; kk < 32; kk += 16) {
            FragA af[4];
            FragBr bf[2];
#pragma unroll
            for (int i = 0; i < 4; i++)
                wmma::load_matrix_sync(af[i], &As[wm * 64 + i * 16][kk], 40);
#pragma unroll
            for (int j = 0; j < 2; j++)
                wmma::load_matrix_sync(bf[j], &Bs[kk][wn * 32 + j * 16], 136);
#pragma unroll
            for (int i = 0; i < 4; i++)
#pragma unroll
                for (int j = 0; j < 2; j++) wmma::mma_sync(acc[i][j], af[i], bf[j], acc[i][j]);
        }
        __syncthreads();
    }

    // ---- store ----
#pragma unroll
    for (int i = 0; i < 4; i++) {
#pragma unroll
        for (int j = 0; j < 2; j++) {
            const int m = m0 + wm * 64 + i * 16;
            const int cg = n0 + wn * 32 + j * 16;
            if (MODE == 1) {
                wmma::store_matrix_sync(out + (size_t)m * Ncols + cg, acc[i][j], Ncols,
                                        wmma::mem_row_major);
            } else {
                // stage fp32 16x16, convert to fp16, scatter to q/k/v [B,H,N,64]
                wmma::store_matrix_sync(stage[warp], acc[i][j], 16, wmma::mem_row_major);
                __syncwarp();
                const int which = cg / Cc;
                const int c = cg % Cc;
                const int h = c >> 6, d0 = c & 63;
                __half* arr = (which == 0) ? g_q : (which == 1) ? g_k : g_v;
                const int b = m >> 10;
                const int r = lid >> 1, h8 = (lid & 1) * 8;
                const float* s = stage[warp] + r * 16 + h8;
                __half2 p[4];
#pragma unroll
                for (int e = 0; e < 4; e++) p[e] = __floats2half2_rn(s[e * 2], s[e * 2 + 1]);
                const int nnr = (m + r) & 1023;
                *(uint4*)(arr + (size_t)((b * Hh + h) * Nn + nnr) * HD + d0 + h8) =
                    *(uint4*)p;
                __syncwarp();
            }
        }
    }
}

// ---------------------------------------------------------------------------
// Flash attention (fp16 wmma): one CTA per (bh, 128-query tile).
// ---------------------------------------------------------------------------
constexpr int OFF_QS = 0;                         // half [128][72]
constexpr int OFF_KV = OFF_QS + 128 * 72 * 2;     // half [128][72]
constexpr int OFF_OS = OFF_KV + 128 * 72 * 2;     // float [128][68]
constexpr int OFF_SS = OFF_OS + 128 * 68 * 4;     // float [128][132]
constexpr int OFF_PS = OFF_SS + 128 * 132 * 4;    // half [128][136]
constexpr int OFF_ST = OFF_PS + 128 * 136 * 2;    // float m/l/alpha [3][128]
constexpr int ATTN_SMEM = OFF_ST + 3 * 128 * 4;   // 175616 B

__global__ void __launch_bounds__(256) attn_kernel() {
    extern __shared__ __align__(16) char smc[];
    __half* Qs  = (__half*)(smc + OFF_QS);
    __half* KVs = (__half*)(smc + OFF_KV);
    float*  Os  = (float*)(smc + OFF_OS);
    float*  Ss  = (float*)(smc + OFF_SS);
    __half* Ps  = (__half*)(smc + OFF_PS);
    float*  m_s = (float*)(smc + OFF_ST);
    float*  l_s = m_s + 128;
    float*  al_s = l_s + 128;

    const int tid = threadIdx.x;
    const int warp = tid >> 5;
    const int n0 = blockIdx.x * 128;
    const int bh = blockIdx.y;
    const __half2* Qg = (const __half2*)(g_q + (size_t)bh * Nn * HD);
    const __half2* Kg = (const __half2*)(g_k + (size_t)bh * Nn * HD);
    const __half2* Vg = (const __half2*)(g_v + (size_t)bh * Nn * HD);

    // load Q tile pre-scaled by 0.125 (exact in fp16)
    const __half2 sc = __floats2half2_rn(0.125f, 0.125f);
#pragma unroll
    for (int t = 0; t < 16; t++) {
        int idx = tid + t * 256;
        int r = idx >> 5, c2 = idx & 31;            // 32 half2 per row (64 halves)
        ((__half2*)Qs)[r * 36 + c2] = __hmul2(Qg[(size_t)(n0 + r) * 32 + c2], sc);
    }
#pragma unroll
    for (int t = 0; t < 8; t++) {
        int idx = tid + t * 256;
        int r = idx >> 4, c4 = idx & 15;
        *(float4*)&Os[r * 68 + c4 * 4] = make_float4(0.f, 0.f, 0.f, 0.f);
    }
    if (tid < 128) {
        m_s[tid] = -1e30f;
        l_s[tid] = 0.0f;
    }
    __syncthreads();

    for (int kt = 0; kt < Nn / 128; kt++) {
        // ---- load K tile ----
#pragma unroll
        for (int t = 0; t < 16; t++) {
            int idx = tid + t * 256;
            int r = idx >> 5, c2 = idx & 31;
            ((__half2*)KVs)[r * 36 + c2] = Kg[(size_t)(kt * 128 + r) * 32 + c2];
        }
        __syncthreads();

        // ---- S = Q K^T (128x128), fp16 in / fp32 acc ----
        {
            const int wm = warp >> 2, wn = warp & 3;  // warp tile 64x32
            FragC accS[4][2];
#pragma unroll
            for (int i = 0; i < 4; i++)
#pragma unroll
                for (int j = 0; j < 2; j++) wmma::fill_fragment(accS[i][j], 0.0f);
#pragma unroll
            for (int kk = 0; kk < HD; kk += 16) {
                FragA af[4];
                FragBc bf[2];
#pragma unroll
                for (int i = 0; i < 4; i++)
                    wmma::load_matrix_sync(af[i], &Qs[(wm * 64 + i * 16) * 72 + kk], 72);
#pragma unroll
                for (int j = 0; j < 2; j++)
                    wmma::load_matrix_sync(bf[j], &KVs[(wn * 32 + j * 16) * 72 + kk], 72);
#pragma unroll
                for (int i = 0; i < 4; i++)
#pragma unroll
                    for (int j = 0; j < 2; j++)
                        wmma::mma_sync(accS[i][j], af[i], bf[j], accS[i][j]);
            }
#pragma unroll
            for (int i = 0; i < 4; i++)
#pragma unroll
                for (int j = 0; j < 2; j++)
                    wmma::store_matrix_sync(&Ss[(wm * 64 + i * 16) * 132 + wn * 32 + j * 16],
                                            accS[i][j], 132, wmma::mem_row_major);
        }
        __syncthreads();

        // ---- online softmax (2 threads per row); P written as fp16 ----
        {
            const int r = tid >> 1;
            const int s = tid & 1;
            const float* row = Ss + r * 132 + s * 64;
            __half* prow = Ps + r * 136 + s * 64;
            const float mo = m_s[r];
            float mx = -1e30f;
#pragma unroll 8
            for (int c = 0; c < 64; c++) mx = fmaxf(mx, row[c]);
            mx = fmaxf(mx, __shfl_xor_sync(0xffffffffu, mx, 1));
            const float mn = fmaxf(mo, mx);
            float ssum = 0.0f;
#pragma unroll 4
            for (int c = 0; c < 64; c += 2) {
                float p0 = __expf(row[c] - mn);
                float p1 = __expf(row[c + 1] - mn);
                ssum += p0 + p1;
                *(__half2*)&prow[c] = __floats2half2_rn(p0, p1);
            }
            ssum += __shfl_xor_sync(0xffffffffu, ssum, 1);
            if (s == 0) {
                const float a = __expf(mo - mn);
                al_s[r] = a;
                m_s[r] = mn;
                l_s[r] = l_s[r] * a + ssum;
            }
        }
        __syncthreads();

        // ---- load V tile (reuse K buffer) + rescale O by alpha ----
#pragma unroll
        for (int t = 0; t < 16; t++) {
            int idx = tid + t * 256;
            int r = idx >> 5, c2 = idx & 31;
            ((__half2*)KVs)[r * 36 + c2] = Vg[(size_t)(kt * 128 + r) * 32 + c2];
        }
#pragma unroll
        for (int t = 0; t < 32; t++) {
            int idx = tid + t * 256;
            int r = idx >> 6, c = idx & 63;
            Os[r * 68 + c] *= al_s[r];
        }
        __syncthreads();

        // ---- O += P V (128x64) ----
        {
            const int wm = warp >> 1, wn = warp & 1;  // warp tile 32x32
            FragC accO[2][2];
#pragma unroll
            for (int i = 0; i < 2; i++)
#pragma unroll
                for (int j = 0; j < 2; j++)
                    wmma::load_matrix_sync(accO[i][j],
                                           &Os[(wm * 32 + i * 16) * 68 + wn * 32 + j * 16], 68,
                                           wmma::mem_row_major);
#pragma unroll
            for (int kk = 0; kk < 128; kk += 16) {
                FragA af[2];
                FragBr bf[2];
#pragma unroll
                for (int i = 0; i < 2; i++)
                    wmma::load_matrix_sync(af[i], &Ps[(wm * 32 + i * 16) * 136 + kk], 136);
#pragma unroll
                for (int j = 0; j < 2; j++)
                    wmma::load_matrix_sync(bf[j], &KVs[kk * 72 + wn * 32 + j * 16], 72);
#pragma unroll
                for (int i = 0; i < 2; i++)
#pragma unroll
                    for (int j = 0; j < 2; j++)
                        wmma::mma_sync(accO[i][j], af[i], bf[j], accO[i][j]);
            }
#pragma unroll
            for (int i = 0; i < 2; i++)
#pragma unroll
                for (int j = 0; j < 2; j++)
                    wmma::store_matrix_sync(&Os[(wm * 32 + i * 16) * 68 + wn * 32 + j * 16],
                                            accO[i][j], 68, wmma::mem_row_major);
        }
        __syncthreads();
    }

    // ---- epilogue: normalize, convert fp16, write to g_ao [B*N, C] at col h*64 ----
    const int b = bh / Hh, h = bh % Hh;
#pragma unroll
    for (int t = 0; t < 16; t++) {
        int idx = tid + t * 256;
        int r = idx >> 5, c2 = idx & 31;              // pairs of columns
        const float inv = 1.0f / l_s[r];
        float o0 = Os[r * 68 + c2 * 2] * inv;
        float o1 = Os[r * 68 + c2 * 2 + 1] * inv;
        *(__half2*)(g_ao + (size_t)(b * Nn + n0 + r) * Cc + h * HD + c2 * 2) =
            __floats2half2_rn(o0, o1);
    }
}

// ---------------------------------------------------------------------------
extern "C" void kernel_launch(void* const* d_in, const int* in_sizes, int n_in,
                              void* d_out, int out_size) {
    const float* x      = (const float*)d_in[0];
    const float* w_qkv  = (const float*)d_in[1];
    const float* b_qkv  = (const float*)d_in[2];
    const float* w_proj = (const float*)d_in[3];
    const float* b_proj = (const float*)d_in[4];
    float* out = (float*)d_out;

    cudaFuncSetAttribute(attn_kernel, cudaFuncAttributeMaxDynamicSharedMemorySize, ATTN_SMEM);

    dim3 blk(256);
    // 1) QKV GEMM: [8192,768] @ [768,2304] + bias -> fp16 scatter to Q/K/V
    gemm_kernel<0><<<dim3((3 * Cc) / 128, Mm / 128), blk>>>(x, w_qkv, b_qkv, nullptr, 3 * Cc);
    // 2) attention per (bh, q-tile)
    attn_kernel<<<dim3(Nn / 128, Bb * Hh), blk, ATTN_SMEM>>>();
    // 3) output projection: [8192,768] @ [768,768] + bias -> d_out (fp32)
    gemm_kernel<1><<<dim3(Cc / 128, Mm / 128), blk>>>(nullptr, w_proj, b_proj, out, Cc);
}

// round 13
// speedup vs baseline: 4.2519x; 1.8159x over previous
#include <cuda_runtime.h>
#include <cuda_fp16.h>
#include <mma.h>
#include <cstdint>

using namespace nvcuda;

constexpr int Bb = 8;
constexpr int Nn = 1024;
constexpr int Cc = 768;
constexpr int Hh = 12;
constexpr int HD = 64;
constexpr int Mm = Bb * Nn;   // 8192

// Scratch (allowed: __device__ globals, no allocation) — fp16 activations/weights
__device__ __align__(16) __half g_q[(size_t)Bb * Hh * Nn * HD];
__device__ __align__(16) __half g_k[(size_t)Bb * Hh * Nn * HD];
__device__ __align__(16) __half g_v[(size_t)Bb * Hh * Nn * HD];
__device__ __align__(16) __half g_ao[(size_t)Mm * Cc];
__device__ __align__(16) __half g_x16[(size_t)Mm * Cc];
__device__ __align__(16) __half g_wq16[(size_t)Cc * 3 * Cc];
__device__ __align__(16) __half g_wp16[(size_t)Cc * Cc];

// ---------------------------------------------------------------------------
// fp32 -> fp16 bulk convert
// ---------------------------------------------------------------------------
__global__ void cvt_fp16(const float* __restrict__ src, __half* __restrict__ dst, int n) {
    int i = (blockIdx.x * blockDim.x + threadIdx.x) * 4;
    if (i < n) {
        float4 v = *(const float4*)(src + i);
        __half2 h0 = __floats2half2_rn(v.x, v.y);
        __half2 h1 = __floats2half2_rn(v.z, v.w);
        *(__half2*)(dst + i) = h0;
        *(__half2*)(dst + i + 2) = h1;
    }
}

// ---------------------------------------------------------------------------
// PTX helpers
// ---------------------------------------------------------------------------
__device__ __forceinline__ uint32_t smem_u32(const void* p) {
    uint32_t a;
    asm("{ .reg .u64 t; cvta.to.shared.u64 t, %1; cvt.u32.u64 %0, t; }" : "=r"(a) : "l"(p));
    return a;
}
__device__ __forceinline__ void ldsm4(uint32_t* r, uint32_t addr) {
    asm volatile("ldmatrix.sync.aligned.m8n8.x4.shared.b16 {%0,%1,%2,%3}, [%4];"
                 : "=r"(r[0]), "=r"(r[1]), "=r"(r[2]), "=r"(r[3]) : "r"(addr));
}
__device__ __forceinline__ void ldsm4t(uint32_t* r, uint32_t addr) {
    asm volatile("ldmatrix.sync.aligned.m8n8.x4.trans.shared.b16 {%0,%1,%2,%3}, [%4];"
                 : "=r"(r[0]), "=r"(r[1]), "=r"(r[2]), "=r"(r[3]) : "r"(addr));
}
__device__ __forceinline__ void mma16816(float* c, const uint32_t* a, const uint32_t* b) {
    asm volatile(
        "mma.sync.aligned.m16n8k16.row.col.f32.f16.f16.f32 "
        "{%0,%1,%2,%3}, {%4,%5,%6,%7}, {%8,%9}, {%0,%1,%2,%3};"
        : "+f"(c[0]), "+f"(c[1]), "+f"(c[2]), "+f"(c[3])
        : "r"(a[0]), "r"(a[1]), "r"(a[2]), "r"(a[3]), "r"(b[0]), "r"(b[1]));
}
__device__ __forceinline__ uint32_t packh2(float lo, float hi) {
    __half2 h = __floats2half2_rn(lo, hi);
    return *(uint32_t*)&h;
}

// ---------------------------------------------------------------------------
// GEMM: C[M,Ncols] = A[M,768] @ Bm[768,Ncols] + bias   (fp16 wmma, 128x128 tile)
// MODE 0: A = g_x16, B = g_wq16 -> scatter fp16 into g_q/g_k/g_v [B,H,N,64]
// MODE 1: A = g_ao,  B = g_wp16 -> fp32 row-major store to out
// Bias folded in as a rank-1 pre-step.
// ---------------------------------------------------------------------------
using FragA  = wmma::fragment<wmma::matrix_a, 16, 16, 16, __half, wmma::row_major>;
using FragBr = wmma::fragment<wmma::matrix_b, 16, 16, 16, __half, wmma::row_major>;
using FragC  = wmma::fragment<wmma::accumulator, 16, 16, 16, float>;

template <int MODE>
__global__ void __launch_bounds__(256) gemm_kernel(const float* __restrict__ bias,
                                                   float* __restrict__ out, int Ncols) {
    __shared__ __align__(16) __half As[128][40];
    __shared__ __align__(16) __half Bs[32][136];
    __shared__ __align__(16) float stage[8][256];

    const __half* A  = (MODE == 0) ? g_x16 : g_ao;
    const __half* Bm = (MODE == 0) ? g_wq16 : g_wp16;

    const int m0 = blockIdx.y * 128;
    const int n0 = blockIdx.x * 128;
    const int tid = threadIdx.x;
    const int warp = tid >> 5;
    const int lid = tid & 31;
    const int wm = warp >> 2;
    const int wn = warp & 3;

    FragC acc[4][2];
#pragma unroll
    for (int i = 0; i < 4; i++)
#pragma unroll
        for (int j = 0; j < 2; j++) wmma::fill_fragment(acc[i][j], 0.0f);

    // ---- bias rank-1 step ----
#pragma unroll
    for (int t = 0; t < 8; t++) {
        int idx = tid + t * 256;
        int r = idx >> 4, c = idx & 15;
        As[r][c] = __float2half((c == 0) ? 1.0f : 0.0f);
    }
#pragma unroll
    for (int t = 0; t < 8; t++) {
        int idx = tid + t * 256;
        int r = idx >> 7, c = idx & 127;
        Bs[r][c] = __float2half((r == 0) ? bias[n0 + c] : 0.0f);
    }
    __syncthreads();
    {
        FragA af[4];
        FragBr bf[2];
#pragma unroll
        for (int i = 0; i < 4; i++) wmma::load_matrix_sync(af[i], &As[wm * 64 + i * 16][0], 40);
#pragma unroll
        for (int j = 0; j < 2; j++) wmma::load_matrix_sync(bf[j], &Bs[0][wn * 32 + j * 16], 136);
#pragma unroll
        for (int i = 0; i < 4; i++)
#pragma unroll
            for (int j = 0; j < 2; j++) wmma::mma_sync(acc[i][j], af[i], bf[j], acc[i][j]);
    }
    __syncthreads();

    // ---- main K loop: 24 chunks of 32 (all-fp16 loads) ----
    for (int kt = 0; kt < Cc / 32; kt++) {
        const int k0 = kt * 32;
#pragma unroll
        for (int t = 0; t < 2; t++) {
            int idx = tid + t * 256;
            int r = idx >> 2, g = idx & 3;
            *(uint4*)&As[r][g * 8] = *(const uint4*)(A + (size_t)(m0 + r) * Cc + k0 + g * 8);
        }
#pragma unroll
        for (int t = 0; t < 2; t++) {
            int idx = tid + t * 256;
            int r = idx >> 4, g = idx & 15;
            *(uint4*)&Bs[r][g * 8] = *(const uint4*)(Bm + (size_t)(k0 + r) * Ncols + n0 + g * 8);
        }
        __syncthreads();
#pragma unroll
        for (int kk = 0; kk < 32; kk += 16) {
            FragA af[4];
            FragBr bf[2];
#pragma unroll
            for (int i = 0; i < 4; i++)
                wmma::load_matrix_sync(af[i], &As[wm * 64 + i * 16][kk], 40);
#pragma unroll
            for (int j = 0; j < 2; j++)
                wmma::load_matrix_sync(bf[j], &Bs[kk][wn * 32 + j * 16], 136);
#pragma unroll
            for (int i = 0; i < 4; i++)
#pragma unroll
                for (int j = 0; j < 2; j++) wmma::mma_sync(acc[i][j], af[i], bf[j], acc[i][j]);
        }
        __syncthreads();
    }

    // ---- store ----
#pragma unroll
    for (int i = 0; i < 4; i++) {
#pragma unroll
        for (int j = 0; j < 2; j++) {
            const int m = m0 + wm * 64 + i * 16;
            const int cg = n0 + wn * 32 + j * 16;
            if (MODE == 1) {
                wmma::store_matrix_sync(out + (size_t)m * Ncols + cg, acc[i][j], Ncols,
                                        wmma::mem_row_major);
            } else {
                wmma::store_matrix_sync(stage[warp], acc[i][j], 16, wmma::mem_row_major);
                __syncwarp();
                const int which = cg / Cc;
                const int c = cg % Cc;
                const int h = c >> 6, d0 = c & 63;
                __half* arr = (which == 0) ? g_q : (which == 1) ? g_k : g_v;
                const int b = m >> 10;
                const int r = lid >> 1, h8 = (lid & 1) * 8;
                const float* s = stage[warp] + r * 16 + h8;
                __half2 p[4];
#pragma unroll
                for (int e = 0; e < 4; e++) p[e] = __floats2half2_rn(s[e * 2], s[e * 2 + 1]);
                const int nnr = (m + r) & 1023;
                *(uint4*)(arr + (size_t)((b * Hh + h) * Nn + nnr) * HD + d0 + h8) = *(uint4*)p;
                __syncwarp();
            }
        }
    }
}

// ---------------------------------------------------------------------------
// Flash attention, FA2-style register-resident (mma.sync.m16n8k16 + ldmatrix).
// CTA: 8 warps, 128 q-rows (16 per warp); K-tile = 64 keys per iteration.
// Per warp: S[16x64] and O[16x64] in registers; softmax entirely in registers.
// ---------------------------------------------------------------------------
constexpr int KT = 64;

__global__ void __launch_bounds__(256, 2) attn_kernel() {
    __shared__ __align__(16) __half Qs[128][72];
    __shared__ __align__(16) __half Ks[KT][72];
    __shared__ __align__(16) __half Vs[KT][72];

    const int tid = threadIdx.x;
    const int warp = tid >> 5;
    const int lane = tid & 31;
    const int n0 = blockIdx.x * 128;
    const int bh = blockIdx.y;
    const __half* Qg = g_q + (size_t)bh * Nn * HD;
    const __half* Kg = g_k + (size_t)bh * Nn * HD;
    const __half* Vg = g_v + (size_t)bh * Nn * HD;

    // ---- load Q tile (128 rows x 64 halves = 1024 uint4), pre-scaled by 0.125 ----
    const __half2 sc = __floats2half2_rn(0.125f, 0.125f);
#pragma unroll
    for (int t = 0; t < 4; t++) {   // R10 BUG was t<2: only half the tile loaded
        int idx = tid + t * 256;
        int r = idx >> 3, g = idx & 7;
        uint4 u = *(const uint4*)(Qg + (size_t)(n0 + r) * HD + g * 8);
        __half2* h = (__half2*)&u;
#pragma unroll
        for (int e = 0; e < 4; e++) h[e] = __hmul2(h[e], sc);
        *(uint4*)&Qs[r][g * 8] = u;
    }
    __syncthreads();

    // ---- Q fragments (held whole kernel): 4 k-steps of m16k16 ----
    uint32_t qa[4][4];
    {
        const uint32_t qs_u = smem_u32(&Qs[0][0]);
        const uint32_t row = warp * 16 + (lane & 15);
        const uint32_t coff = (lane >> 4) * 8;
#pragma unroll
        for (int kk = 0; kk < 4; kk++)
            ldsm4(qa[kk], qs_u + (row * 72 + kk * 16 + coff) * 2);
    }

    float o[8][4];
#pragma unroll
    for (int h = 0; h < 8; h++)
#pragma unroll
        for (int e = 0; e < 4; e++) o[h][e] = 0.0f;
    float m0 = -1e30f, m1 = -1e30f, l0 = 0.0f, l1 = 0.0f;

    const uint32_t ks_u = smem_u32(&Ks[0][0]);
    const uint32_t vs_u = smem_u32(&Vs[0][0]);
    const uint32_t krow = (lane & 7);
    const uint32_t kcol = (lane >> 3) * 8;

    for (int kt = 0; kt < Nn / KT; kt++) {
        __syncthreads();  // previous iteration's reads of Ks/Vs complete
        // ---- load K, V tiles (64x64 fp16 each) ----
#pragma unroll
        for (int t = 0; t < 2; t++) {
            int idx = tid + t * 256;
            int r = idx >> 3, g = idx & 7;
            *(uint4*)&Ks[r][g * 8] = *(const uint4*)(Kg + (size_t)(kt * KT + r) * HD + g * 8);
            *(uint4*)&Vs[r][g * 8] = *(const uint4*)(Vg + (size_t)(kt * KT + r) * HD + g * 8);
        }
        __syncthreads();

        // ---- S = Q K^T : 8 key-tiles (n8) x 4 k-steps ----
        float s[8][4];
#pragma unroll
        for (int j = 0; j < 8; j++) {
            s[j][0] = s[j][1] = s[j][2] = s[j][3] = 0.0f;
            const uint32_t base = ks_u + (((j * 8 + krow) * 72) + kcol) * 2;
            uint32_t kr[4];
            ldsm4(kr, base);            // hd 0..31 -> k-steps 0,1
            mma16816(s[j], qa[0], kr);
            mma16816(s[j], qa[1], kr + 2);
            ldsm4(kr, base + 64);       // hd 32..63 -> k-steps 2,3
            mma16816(s[j], qa[2], kr);
            mma16816(s[j], qa[3], kr + 2);
        }

        // ---- online softmax in registers (rows r = lane>>2 and r+8) ----
        float mx0 = -1e30f, mx1 = -1e30f;
#pragma unroll
        for (int j = 0; j < 8; j++) {
            mx0 = fmaxf(mx0, fmaxf(s[j][0], s[j][1]));
            mx1 = fmaxf(mx1, fmaxf(s[j][2], s[j][3]));
        }
        mx0 = fmaxf(mx0, __shfl_xor_sync(0xffffffffu, mx0, 1));
        mx0 = fmaxf(mx0, __shfl_xor_sync(0xffffffffu, mx0, 2));
        mx1 = fmaxf(mx1, __shfl_xor_sync(0xffffffffu, mx1, 1));
        mx1 = fmaxf(mx1, __shfl_xor_sync(0xffffffffu, mx1, 2));
        const float mn0 = fmaxf(m0, mx0), mn1 = fmaxf(m1, mx1);
        const float al0 = __expf(m0 - mn0), al1 = __expf(m1 - mn1);
        m0 = mn0; m1 = mn1;

        float sl0 = 0.0f, sl1 = 0.0f;
        uint32_t pa[4][4];  // P as A-fragments (k-step kk covers key-tiles 2kk, 2kk+1)
#pragma unroll
        for (int j = 0; j < 8; j++) {
            float p0 = __expf(s[j][0] - mn0);
            float p1 = __expf(s[j][1] - mn0);
            float p2 = __expf(s[j][2] - mn1);
            float p3 = __expf(s[j][3] - mn1);
            sl0 += p0 + p1;
            sl1 += p2 + p3;
            pa[j >> 1][(j & 1) * 2]     = packh2(p0, p1);
            pa[j >> 1][(j & 1) * 2 + 1] = packh2(p2, p3);
        }
        sl0 += __shfl_xor_sync(0xffffffffu, sl0, 1);
        sl0 += __shfl_xor_sync(0xffffffffu, sl0, 2);
        sl1 += __shfl_xor_sync(0xffffffffu, sl1, 1);
        sl1 += __shfl_xor_sync(0xffffffffu, sl1, 2);
        l0 = l0 * al0 + sl0;
        l1 = l1 * al1 + sl1;
#pragma unroll
        for (int h = 0; h < 8; h++) {
            o[h][0] *= al0; o[h][1] *= al0;
            o[h][2] *= al1; o[h][3] *= al1;
        }

        // ---- O += P V : 4 k-steps (16 keys each) x 8 hd-tiles ----
#pragma unroll
        for (int kk = 0; kk < 4; kk++) {
            const uint32_t vbase = vs_u + (((kk * 16 + (lane & 15)) * 72) + (lane >> 4) * 8) * 2;
#pragma unroll
            for (int hp = 0; hp < 4; hp++) {
                uint32_t vr[4];
                ldsm4t(vr, vbase + hp * 32);  // hd-tiles 2hp, 2hp+1
                mma16816(o[2 * hp],     pa[kk], vr);
                mma16816(o[2 * hp + 1], pa[kk], vr + 2);
            }
        }
    }

    // ---- epilogue: normalize, write fp16 to g_ao [B*N, C] at col head*64 ----
    const int b = bh / Hh, head = bh % Hh;
    const float inv0 = 1.0f / l0, inv1 = 1.0f / l1;
    const int row0 = n0 + warp * 16 + (lane >> 2);
    __half* po0 = g_ao + (size_t)(b * Nn + row0) * Cc + head * HD;
    __half* po1 = po0 + (size_t)8 * Cc;
    const int cb = (lane & 3) * 2;
#pragma unroll
    for (int h = 0; h < 8; h++) {
        *(__half2*)(po0 + h * 8 + cb) = __floats2half2_rn(o[h][0] * inv0, o[h][1] * inv0);
        *(__half2*)(po1 + h * 8 + cb) = __floats2half2_rn(o[h][2] * inv1, o[h][3] * inv1);
    }
}

// ---------------------------------------------------------------------------
extern "C" void kernel_launch(void* const* d_in, const int* in_sizes, int n_in,
                              void* d_out, int out_size) {
    const float* x      = (const float*)d_in[0];
    const float* w_qkv  = (const float*)d_in[1];
    const float* b_qkv  = (const float*)d_in[2];
    const float* w_proj = (const float*)d_in[3];
    const float* b_proj = (const float*)d_in[4];
    float* out = (float*)d_out;

    // 0) bulk fp32->fp16 converts (x, w_qkv, w_proj)
    static __half* px = nullptr;  // resolve device-symbol addresses host-side once
    static __half* pwq = nullptr;
    static __half* pwp = nullptr;
    if (!px) {
        cudaGetSymbolAddress((void**)&px, g_x16);
        cudaGetSymbolAddress((void**)&pwq, g_wq16);
        cudaGetSymbolAddress((void**)&pwp, g_wp16);
    }
    cvt_fp16<<<(Mm * Cc) / 1024, 256>>>(x, px, Mm * Cc);
    cvt_fp16<<<(Cc * 3 * Cc) / 1024, 256>>>(w_qkv, pwq, Cc * 3 * Cc);
    cvt_fp16<<<(Cc * Cc) / 1024, 256>>>(w_proj, pwp, Cc * Cc);

    dim3 blk(256);
    // 1) QKV GEMM: [8192,768] @ [768,2304] + bias -> fp16 scatter to Q/K/V
    gemm_kernel<0><<<dim3((3 * Cc) / 128, Mm / 128), blk>>>(b_qkv, nullptr, 3 * Cc);
    // 2) attention per (bh, 128-q-tile)
    attn_kernel<<<dim3(Nn / 128, Bb * Hh), blk>>>();
    // 3) output projection: [8192,768] @ [768,768] + bias -> d_out (fp32)
    gemm_kernel<1><<<dim3(Cc / 128, Mm / 128), blk>>>(b_proj, out, Cc);
}

// round 14
// speedup vs baseline: 4.4692x; 1.0511x over previous
#include <cuda_runtime.h>
#include <cuda_fp16.h>
#include <cstdint>

constexpr int Bb = 8;
constexpr int Nn = 1024;
constexpr int Cc = 768;
constexpr int Hh = 12;
constexpr int HD = 64;
constexpr int Mm = Bb * Nn;   // 8192

// Scratch (allowed: __device__ globals, no allocation) — fp16 activations/weights
__device__ __align__(16) __half g_q[(size_t)Bb * Hh * Nn * HD];
__device__ __align__(16) __half g_k[(size_t)Bb * Hh * Nn * HD];
__device__ __align__(16) __half g_v[(size_t)Bb * Hh * Nn * HD];
__device__ __align__(16) __half g_ao[(size_t)Mm * Cc];
__device__ __align__(16) __half g_x16[(size_t)Mm * Cc];
__device__ __align__(16) __half g_wq16[(size_t)Cc * 3 * Cc];
__device__ __align__(16) __half g_wp16[(size_t)Cc * Cc];

// ---------------------------------------------------------------------------
// fp32 -> fp16 bulk convert
// ---------------------------------------------------------------------------
__global__ void cvt_fp16(const float* __restrict__ src, __half* __restrict__ dst, int n) {
    int i = (blockIdx.x * blockDim.x + threadIdx.x) * 4;
    if (i < n) {
        float4 v = *(const float4*)(src + i);
        *(__half2*)(dst + i)     = __floats2half2_rn(v.x, v.y);
        *(__half2*)(dst + i + 2) = __floats2half2_rn(v.z, v.w);
    }
}

// ---------------------------------------------------------------------------
// PTX helpers
// ---------------------------------------------------------------------------
__device__ __forceinline__ uint32_t smem_u32(const void* p) {
    uint32_t a;
    asm("{ .reg .u64 t; cvta.to.shared.u64 t, %1; cvt.u32.u64 %0, t; }" : "=r"(a) : "l"(p));
    return a;
}
__device__ __forceinline__ void ldsm4(uint32_t* r, uint32_t addr) {
    asm volatile("ldmatrix.sync.aligned.m8n8.x4.shared.b16 {%0,%1,%2,%3}, [%4];"
                 : "=r"(r[0]), "=r"(r[1]), "=r"(r[2]), "=r"(r[3]) : "r"(addr));
}
__device__ __forceinline__ void ldsm4t(uint32_t* r, uint32_t addr) {
    asm volatile("ldmatrix.sync.aligned.m8n8.x4.trans.shared.b16 {%0,%1,%2,%3}, [%4];"
                 : "=r"(r[0]), "=r"(r[1]), "=r"(r[2]), "=r"(r[3]) : "r"(addr));
}
__device__ __forceinline__ void mma16816(float* c, const uint32_t* a, const uint32_t* b) {
    asm volatile(
        "mma.sync.aligned.m16n8k16.row.col.f32.f16.f16.f32 "
        "{%0,%1,%2,%3}, {%4,%5,%6,%7}, {%8,%9}, {%0,%1,%2,%3};"
        : "+f"(c[0]), "+f"(c[1]), "+f"(c[2]), "+f"(c[3])
        : "r"(a[0]), "r"(a[1]), "r"(a[2]), "r"(a[3]), "r"(b[0]), "r"(b[1]));
}
__device__ __forceinline__ uint32_t packh2(float lo, float hi) {
    __half2 h = __floats2half2_rn(lo, hi);
    return *(uint32_t*)&h;
}
__device__ __forceinline__ void cp16(uint32_t saddr, const void* gaddr) {
    asm volatile("cp.async.cg.shared.global [%0], [%1], 16;" :: "r"(saddr), "l"(gaddr));
}
__device__ __forceinline__ void cp_commit() { asm volatile("cp.async.commit_group;"); }

// ---------------------------------------------------------------------------
// Raw-mma GEMM: C[M,Ncols] = A[M,768] @ Bm[768,Ncols] + bias
// CTA tile 128x256, 8 warps (2x4), warp tile 64x64, K-chunk 64,
// 2-stage cp.async double buffer.
// MODE 0: A = g_x16, B = g_wq16 -> scatter fp16 into g_q/g_k/g_v [B,H,N,64]
// MODE 1: A = g_ao,  B = g_wp16 -> fp32 row-major store to out
// ---------------------------------------------------------------------------
constexpr int TN = 256;
constexpr int KC = 64;                 // halves per K chunk
constexpr int NCH = Cc / KC;           // 12
constexpr int ASTR = 72;               // As row stride (halves)
constexpr int BSTR = 264;              // Bs row stride (halves)
constexpr int A_ST_BYTES = 128 * ASTR * 2;   // 18432
constexpr int B_ST_BYTES = KC * BSTR * 2;    // 33792
constexpr int OFF_B0 = 2 * A_ST_BYTES;       // 36864
constexpr int GEMM_SMEM = OFF_B0 + 2 * B_ST_BYTES;  // 104448

template <int MODE>
__global__ void __launch_bounds__(256, 1) gemm_kernel(const float* __restrict__ bias,
                                                      float* __restrict__ out, int Ncols) {
    extern __shared__ __align__(16) char smc[];
    const uint32_t sbase = smem_u32(smc);

    const __half* A  = (MODE == 0) ? g_x16 : g_ao;
    const __half* Bm = (MODE == 0) ? g_wq16 : g_wp16;

    const int m0 = blockIdx.y * 128;
    const int n0 = blockIdx.x * TN;
    const int tid = threadIdx.x;
    const int warp = tid >> 5;
    const int lane = tid & 31;
    const int wm = warp >> 2;   // 0..1 -> 64-row band
    const int wn = warp & 3;    // 0..3 -> 64-col band

    // ---- async loaders ----
    auto load_chunk = [&](int ch, int buf) {
        const int k0 = ch * KC;
        // A: 128 rows x 64 halves (128B/row) = 1024 x 16B
        const uint32_t abase = sbase + buf * A_ST_BYTES;
#pragma unroll
        for (int t = 0; t < 4; t++) {
            int idx = tid + t * 256;
            int r = idx >> 3, seg = idx & 7;
            cp16(abase + (uint32_t)(r * (ASTR * 2) + seg * 16),
                 A + (size_t)(m0 + r) * Cc + k0 + seg * 8);
        }
        // B: 64 rows x 256 halves (512B/row) = 2048 x 16B
        const uint32_t bbase = sbase + OFF_B0 + buf * B_ST_BYTES;
#pragma unroll
        for (int t = 0; t < 8; t++) {
            int idx = tid + t * 256;
            int r = idx >> 5, seg = idx & 31;
            cp16(bbase + (uint32_t)(r * (BSTR * 2) + seg * 16),
                 Bm + (size_t)(k0 + r) * Ncols + n0 + seg * 8);
        }
        cp_commit();
    };

    float c[4][8][4];
#pragma unroll
    for (int mf = 0; mf < 4; mf++)
#pragma unroll
        for (int nt = 0; nt < 8; nt++)
#pragma unroll
            for (int e = 0; e < 4; e++) c[mf][nt][e] = 0.0f;

    load_chunk(0, 0);
    load_chunk(1, 1);

    // per-lane fragment addresses
    const uint32_t a_row = (uint32_t)(wm * 64) + (lane & 15);
    const uint32_t a_coff = (uint32_t)(lane >> 4) * 8;
    const uint32_t b_krow = (uint32_t)(lane & 15);
    const uint32_t b_coff = (uint32_t)(wn * 64) + (uint32_t)(lane >> 4) * 8;

    for (int ch = 0; ch < NCH; ch++) {
        const int buf = ch & 1;
        if (ch + 1 < NCH) {
            asm volatile("cp.async.wait_group 1;" ::: "memory");
        } else {
            asm volatile("cp.async.wait_group 0;" ::: "memory");
        }
        __syncthreads();

        const uint32_t abase = sbase + buf * A_ST_BYTES;
        const uint32_t bbase = sbase + OFF_B0 + buf * B_ST_BYTES;
#pragma unroll
        for (int kk = 0; kk < 4; kk++) {
            uint32_t a[4][4];
#pragma unroll
            for (int mf = 0; mf < 4; mf++)
                ldsm4(a[mf], abase + ((a_row + mf * 16) * ASTR + kk * 16 + a_coff) * 2);
            uint32_t b[4][4];
#pragma unroll
            for (int np = 0; np < 4; np++)
                ldsm4t(b[np], bbase + ((kk * 16 + b_krow) * BSTR + b_coff + np * 16) * 2);
#pragma unroll
            for (int mf = 0; mf < 4; mf++)
#pragma unroll
                for (int nt = 0; nt < 8; nt++)
                    mma16816(c[mf][nt], a[mf], b[nt >> 1] + (nt & 1) * 2);
        }
        __syncthreads();
        if (ch + 2 < NCH) load_chunk(ch + 2, buf);
    }

    // ---- epilogue: bias + store (no staging) ----
    // acc layout: rows r0 = mf*16 + lane>>2, r1 = r0+8; cols nt*8 + (lane&3)*2 (+0,+1)
    const int ncol0 = n0 + wn * 64;
    float2 bias2[8];
#pragma unroll
    for (int nt = 0; nt < 8; nt++) {
        const int n = ncol0 + nt * 8 + (lane & 3) * 2;
        bias2[nt] = *(const float2*)(bias + n);
    }

    if (MODE == 1) {
#pragma unroll
        for (int mf = 0; mf < 4; mf++) {
            const int r0 = m0 + wm * 64 + mf * 16 + (lane >> 2);
#pragma unroll
            for (int nt = 0; nt < 8; nt++) {
                const int n = ncol0 + nt * 8 + (lane & 3) * 2;
                *(float2*)(out + (size_t)r0 * Ncols + n) =
                    make_float2(c[mf][nt][0] + bias2[nt].x, c[mf][nt][1] + bias2[nt].y);
                *(float2*)(out + (size_t)(r0 + 8) * Ncols + n) =
                    make_float2(c[mf][nt][2] + bias2[nt].x, c[mf][nt][3] + bias2[nt].y);
            }
        }
    } else {
        // the 64-col warp band sits inside one 64-wide head chunk
        const int which = ncol0 / Cc;
        const int rem = ncol0 % Cc;
        const int h = rem >> 6;
        __half* arr = (which == 0) ? g_q : (which == 1) ? g_k : g_v;
#pragma unroll
        for (int mf = 0; mf < 4; mf++) {
            const int r0 = m0 + wm * 64 + mf * 16 + (lane >> 2);
            const int b0 = r0 >> 10, nr0 = r0 & 1023;
            const int r1 = r0 + 8;
            const int b1 = r1 >> 10, nr1 = r1 & 1023;
            __half* p0 = arr + (size_t)((b0 * Hh + h) * Nn + nr0) * HD;
            __half* p1 = arr + (size_t)((b1 * Hh + h) * Nn + nr1) * HD;
#pragma unroll
            for (int nt = 0; nt < 8; nt++) {
                const int d = (rem & 63) + nt * 8 + (lane & 3) * 2;
                *(__half2*)(p0 + d) =
                    __floats2half2_rn(c[mf][nt][0] + bias2[nt].x, c[mf][nt][1] + bias2[nt].y);
                *(__half2*)(p1 + d) =
                    __floats2half2_rn(c[mf][nt][2] + bias2[nt].x, c[mf][nt][3] + bias2[nt].y);
            }
        }
    }
}

// ---------------------------------------------------------------------------
// Flash attention, FA2-style register-resident (unchanged from R13).
// ---------------------------------------------------------------------------
constexpr int KT = 64;

__global__ void __launch_bounds__(256, 2) attn_kernel() {
    __shared__ __align__(16) __half Qs[128][72];
    __shared__ __align__(16) __half Ks[KT][72];
    __shared__ __align__(16) __half Vs[KT][72];

    const int tid = threadIdx.x;
    const int warp = tid >> 5;
    const int lane = tid & 31;
    const int n0 = blockIdx.x * 128;
    const int bh = blockIdx.y;
    const __half* Qg = g_q + (size_t)bh * Nn * HD;
    const __half* Kg = g_k + (size_t)bh * Nn * HD;
    const __half* Vg = g_v + (size_t)bh * Nn * HD;

    const __half2 sc = __floats2half2_rn(0.125f, 0.125f);
#pragma unroll
    for (int t = 0; t < 4; t++) {
        int idx = tid + t * 256;
        int r = idx >> 3, g = idx & 7;
        uint4 u = *(const uint4*)(Qg + (size_t)(n0 + r) * HD + g * 8);
        __half2* h = (__half2*)&u;
#pragma unroll
        for (int e = 0; e < 4; e++) h[e] = __hmul2(h[e], sc);
        *(uint4*)&Qs[r][g * 8] = u;
    }
    __syncthreads();

    uint32_t qa[4][4];
    {
        const uint32_t qs_u = smem_u32(&Qs[0][0]);
        const uint32_t row = warp * 16 + (lane & 15);
        const uint32_t coff = (lane >> 4) * 8;
#pragma unroll
        for (int kk = 0; kk < 4; kk++)
            ldsm4(qa[kk], qs_u + (row * 72 + kk * 16 + coff) * 2);
    }

    float o[8][4];
#pragma unroll
    for (int h = 0; h < 8; h++)
#pragma unroll
        for (int e = 0; e < 4; e++) o[h][e] = 0.0f;
    float m0 = -1e30f, m1 = -1e30f, l0 = 0.0f, l1 = 0.0f;

    const uint32_t ks_u = smem_u32(&Ks[0][0]);
    const uint32_t vs_u = smem_u32(&Vs[0][0]);
    const uint32_t krow = (lane & 7);
    const uint32_t kcol = (lane >> 3) * 8;

    for (int kt = 0; kt < Nn / KT; kt++) {
        __syncthreads();
#pragma unroll
        for (int t = 0; t < 2; t++) {
            int idx = tid + t * 256;
            int r = idx >> 3, g = idx & 7;
            *(uint4*)&Ks[r][g * 8] = *(const uint4*)(Kg + (size_t)(kt * KT + r) * HD + g * 8);
            *(uint4*)&Vs[r][g * 8] = *(const uint4*)(Vg + (size_t)(kt * KT + r) * HD + g * 8);
        }
        __syncthreads();

        float s[8][4];
#pragma unroll
        for (int j = 0; j < 8; j++) {
            s[j][0] = s[j][1] = s[j][2] = s[j][3] = 0.0f;
            const uint32_t base = ks_u + (((j * 8 + krow) * 72) + kcol) * 2;
            uint32_t kr[4];
            ldsm4(kr, base);
            mma16816(s[j], qa[0], kr);
            mma16816(s[j], qa[1], kr + 2);
            ldsm4(kr, base + 64);
            mma16816(s[j], qa[2], kr);
            mma16816(s[j], qa[3], kr + 2);
        }

        float mx0 = -1e30f, mx1 = -1e30f;
#pragma unroll
        for (int j = 0; j < 8; j++) {
            mx0 = fmaxf(mx0, fmaxf(s[j][0], s[j][1]));
            mx1 = fmaxf(mx1, fmaxf(s[j][2], s[j][3]));
        }
        mx0 = fmaxf(mx0, __shfl_xor_sync(0xffffffffu, mx0, 1));
        mx0 = fmaxf(mx0, __shfl_xor_sync(0xffffffffu, mx0, 2));
        mx1 = fmaxf(mx1, __shfl_xor_sync(0xffffffffu, mx1, 1));
        mx1 = fmaxf(mx1, __shfl_xor_sync(0xffffffffu, mx1, 2));
        const float mn0 = fmaxf(m0, mx0), mn1 = fmaxf(m1, mx1);
        const float al0 = __expf(m0 - mn0), al1 = __expf(m1 - mn1);
        m0 = mn0; m1 = mn1;

        float sl0 = 0.0f, sl1 = 0.0f;
        uint32_t pa[4][4];
#pragma unroll
        for (int j = 0; j < 8; j++) {
            float p0 = __expf(s[j][0] - mn0);
            float p1 = __expf(s[j][1] - mn0);
            float p2 = __expf(s[j][2] - mn1);
            float p3 = __expf(s[j][3] - mn1);
            sl0 += p0 + p1;
            sl1 += p2 + p3;
            pa[j >> 1][(j & 1) * 2]     = packh2(p0, p1);
            pa[j >> 1][(j & 1) * 2 + 1] = packh2(p2, p3);
        }
        sl0 += __shfl_xor_sync(0xffffffffu, sl0, 1);
        sl0 += __shfl_xor_sync(0xffffffffu, sl0, 2);
        sl1 += __shfl_xor_sync(0xffffffffu, sl1, 1);
        sl1 += __shfl_xor_sync(0xffffffffu, sl1, 2);
        l0 = l0 * al0 + sl0;
        l1 = l1 * al1 + sl1;
#pragma unroll
        for (int h = 0; h < 8; h++) {
            o[h][0] *= al0; o[h][1] *= al0;
            o[h][2] *= al1; o[h][3] *= al1;
        }

#pragma unroll
        for (int kk = 0; kk < 4; kk++) {
            const uint32_t vbase = vs_u + (((kk * 16 + (lane & 15)) * 72) + (lane >> 4) * 8) * 2;
#pragma unroll
            for (int hp = 0; hp < 4; hp++) {
                uint32_t vr[4];
                ldsm4t(vr, vbase + hp * 32);
                mma16816(o[2 * hp],     pa[kk], vr);
                mma16816(o[2 * hp + 1], pa[kk], vr + 2);
            }
        }
    }

    const int b = bh / Hh, head = bh % Hh;
    const float inv0 = 1.0f / l0, inv1 = 1.0f / l1;
    const int row0 = n0 + warp * 16 + (lane >> 2);
    __half* po0 = g_ao + (size_t)(b * Nn + row0) * Cc + head * HD;
    __half* po1 = po0 + (size_t)8 * Cc;
    const int cb = (lane & 3) * 2;
#pragma unroll
    for (int h = 0; h < 8; h++) {
        *(__half2*)(po0 + h * 8 + cb) = __floats2half2_rn(o[h][0] * inv0, o[h][1] * inv0);
        *(__half2*)(po1 + h * 8 + cb) = __floats2half2_rn(o[h][2] * inv1, o[h][3] * inv1);
    }
}

// ---------------------------------------------------------------------------
extern "C" void kernel_launch(void* const* d_in, const int* in_sizes, int n_in,
                              void* d_out, int out_size) {
    const float* x      = (const float*)d_in[0];
    const float* w_qkv  = (const float*)d_in[1];
    const float* b_qkv  = (const float*)d_in[2];
    const float* w_proj = (const float*)d_in[3];
    const float* b_proj = (const float*)d_in[4];
    float* out = (float*)d_out;

    static __half* px = nullptr;
    static __half* pwq = nullptr;
    static __half* pwp = nullptr;
    static bool attr_set = false;
    if (!px) {
        cudaGetSymbolAddress((void**)&px, g_x16);
        cudaGetSymbolAddress((void**)&pwq, g_wq16);
        cudaGetSymbolAddress((void**)&pwp, g_wp16);
    }
    if (!attr_set) {
        cudaFuncSetAttribute(gemm_kernel<0>, cudaFuncAttributeMaxDynamicSharedMemorySize,
                             GEMM_SMEM);
        cudaFuncSetAttribute(gemm_kernel<1>, cudaFuncAttributeMaxDynamicSharedMemorySize,
                             GEMM_SMEM);
        attr_set = true;
    }

    // 0) bulk fp32->fp16 converts
    cvt_fp16<<<(Mm * Cc) / 1024, 256>>>(x, px, Mm * Cc);
    cvt_fp16<<<(Cc * 3 * Cc) / 1024, 256>>>(w_qkv, pwq, Cc * 3 * Cc);
    cvt_fp16<<<(Cc * Cc) / 1024, 256>>>(w_proj, pwp, Cc * Cc);

    dim3 blk(256);
    // 1) QKV GEMM: [8192,768] @ [768,2304] + bias -> fp16 scatter to Q/K/V
    gemm_kernel<0><<<dim3((3 * Cc) / TN, Mm / 128), blk, GEMM_SMEM>>>(b_qkv, nullptr, 3 * Cc);
    // 2) attention per (bh, 128-q-tile)
    attn_kernel<<<dim3(Nn / 128, Bb * Hh), blk>>>();
    // 3) output projection: [8192,768] @ [768,768] + bias -> d_out (fp32)
    gemm_kernel<1><<<dim3(Cc / TN, Mm / 128), blk, GEMM_SMEM>>>(b_proj, out, Cc);
}